// round 6
// baseline (speedup 1.0000x reference)
#include <cuda_runtime.h>
#include <cstdint>

#define T_STEPS 2048
#define BATCH   64
#define H       256
#define HHALF   128
#define TBH     (T_STEPS * BATCH * H)

typedef unsigned long long u64;

// Scratch (no cudaMalloc allowed): packed W_ih and precomputed xproj.
__device__ u64   g_Wp[(H / 2) * H];      // Wp[u][c] = pack(W_ih[c][2u], W_ih[c][2u+1])
__device__ float g_xproj[(size_t)TBH];   // [T*B][H]

// ---------------------------------------------------------------------------
// helpers
// ---------------------------------------------------------------------------
__device__ __forceinline__ void fma2(u64& d, u64 a, u64 b)
{
    asm("fma.rn.f32x2 %0, %1, %2, %0;" : "+l"(d) : "l"(a), "l"(b));
}
__device__ __forceinline__ float fold2(u64 v)
{
    float lo, hi;
    asm("mov.b64 {%0, %1}, %2;" : "=f"(lo), "=f"(hi) : "l"(v));
    return lo + hi;
}
__device__ __forceinline__ uint32_t smem_u32(const void* p)
{
    uint32_t a;
    asm("{ .reg .u64 t; cvta.to.shared.u64 t, %1; cvt.u32.u64 %0, t; }"
        : "=r"(a) : "l"(p));
    return a;
}
__device__ __forceinline__ uint32_t mapa_u32(uint32_t la, uint32_t rank)
{
    uint32_t ra;
    asm("mapa.shared::cluster.u32 %0, %1, %2;" : "=r"(ra) : "r"(la), "r"(rank));
    return ra;
}
// tanh(x) = 1 - 2/(1+e^{2x}); __expf + fast div: ~6 ops, rel err ~1e-6.
// Large |x| degrades gracefully (inf -> 1, 0 -> -1).
__device__ __forceinline__ float fast_tanh(float x)
{
    float e = __expf(2.0f * x);
    return 1.0f - __fdividef(2.0f, 1.0f + e);
}

// ---------------------------------------------------------------------------
// Kernel 1: pack W_ih into pair layout (u64 transpose).
// ---------------------------------------------------------------------------
__global__ void pack_wih_kernel(const float* __restrict__ W, u64* __restrict__ Wp)
{
    __shared__ u64 tile[32][33];
    const int u0 = (blockIdx.x & 3) * 32;
    const int c0 = (blockIdx.x >> 2) * 32;
    const u64* ullW = reinterpret_cast<const u64*>(W);
    tile[threadIdx.y][threadIdx.x] = ullW[(c0 + threadIdx.y) * (H / 2) + (u0 + threadIdx.x)];
    __syncthreads();
    Wp[(u0 + threadIdx.y) * H + (c0 + threadIdx.x)] = tile[threadIdx.x][threadIdx.y];
}

// ---------------------------------------------------------------------------
// Kernel 2: xproj[r][c] = sum_i x[r][i]*W_ih[c][i] + b_ih[c] + b_hh[c]
// 128 threads/block, 32 rows/block. Thread tile: 8 rows x 8 strided cols.
// 1 LDG per 8 fma2 -> LDG issue well under the FMA floor.
// ---------------------------------------------------------------------------
__global__ __launch_bounds__(128, 2)
void xproj_kernel(const float* __restrict__ x, const u64* __restrict__ Wp,
                  const float* __restrict__ b_ih, const float* __restrict__ b_hh,
                  float* __restrict__ xproj)
{
    __shared__ __align__(16) u64 xs[32][H / 2];   // 32 rows x 128 k-pairs = 32KB

    const int tid = threadIdx.x;
    const size_t row0 = (size_t)blockIdx.x * 32;

    // stage x tile: 2048 float4 / 128 threads = 16 each
    const float4* xg = reinterpret_cast<const float4*>(x + row0 * H);
    float4* xsf = reinterpret_cast<float4*>(&xs[0][0]);
    #pragma unroll
    for (int i = 0; i < 16; i++) xsf[tid + i * 128] = xg[tid + i * 128];
    __syncthreads();

    const int lane = tid & 31;   // cols = lane + 32*i
    const int wrp  = tid >> 5;   // rows r0..r0+7
    const int r0   = 8 * wrp;

    u64 acc[8][8];
    #pragma unroll
    for (int m = 0; m < 8; m++)
        #pragma unroll
        for (int i = 0; i < 8; i++) acc[m][i] = 0ull;

    #pragma unroll 2
    for (int u = 0; u < H / 2; u++) {
        u64 w[8];
        #pragma unroll
        for (int i = 0; i < 8; i++) w[i] = __ldg(&Wp[u * H + lane + 32 * i]);
        u64 xv[8];
        #pragma unroll
        for (int m = 0; m < 8; m++) xv[m] = xs[r0 + m][u];
        #pragma unroll
        for (int m = 0; m < 8; m++)
            #pragma unroll
            for (int i = 0; i < 8; i++) fma2(acc[m][i], xv[m], w[i]);
    }

    float bias[8];
    #pragma unroll
    for (int i = 0; i < 8; i++) {
        const int c = lane + 32 * i;
        bias[i] = b_ih[c] + b_hh[c];
    }

    #pragma unroll
    for (int m = 0; m < 8; m++) {
        float* orow = xproj + (row0 + r0 + m) * H;
        #pragma unroll
        for (int i = 0; i < 8; i++)
            orow[lane + 32 * i] = fold2(acc[m][i]) + bias[i];
    }
}

// ---------------------------------------------------------------------------
// Kernel 3: scan, 2-CTA cluster per batch row, tag-in-data handshake,
// LOCAL-FIRST k split: warp s computes its 16-k slice from the OWN-rank half
// (lands locally, ready early) while the peer half's DSMEM stores (~215cyc)
// are still in flight, then polls + computes the peer 16-k slice.
// ---------------------------------------------------------------------------
__global__ void __cluster_dims__(2, 1, 1) __launch_bounds__(256, 1)
rnn_scan_kernel(const float* __restrict__ xproj, const float* __restrict__ hx,
                const float* __restrict__ W_hh, float* __restrict__ out,
                float* __restrict__ hlast)
{
    __shared__ __align__(16) u64 h_tag[2][H];      // (value, tag) per element
    __shared__ __align__(16) float part[2][8][HHALF];

    const int tid = threadIdx.x;
    uint32_t rank;
    asm("mov.u32 %0, %%cluster_ctarank;" : "=r"(rank));
    const int b  = blockIdx.x >> 1;
    const int j0 = (int)rank * HHALF;

    const int s    = tid >> 5;
    const int lane = tid & 31;
    const int jl   = 4 * lane;                       // 4 output columns
    const int kL   = (int)rank * HHALF + 16 * s;     // local-half k slice
    const int kP   = (int)(rank ^ 1u) * HHALF + 16 * s; // peer-half k slice

    // --- W_hh slices in registers as k-pairs
    u64 wL[4][8], wP[4][8];
    {
        #pragma unroll
        for (int r = 0; r < 4; r++) {
            const ulonglong2* pL = reinterpret_cast<const ulonglong2*>(
                W_hh + (size_t)(j0 + jl + r) * H + kL);
            const ulonglong2* pP = reinterpret_cast<const ulonglong2*>(
                W_hh + (size_t)(j0 + jl + r) * H + kP);
            #pragma unroll
            for (int q = 0; q < 4; q++) {
                ulonglong2 vL = pL[q];
                wL[r][2 * q]     = vL.x;
                wL[r][2 * q + 1] = vL.y;
                ulonglong2 vP = pP[q];
                wP[r][2 * q]     = vP.x;
                wP[r][2 * q + 1] = vP.y;
            }
        }
    }

    // --- init: buffer0 = (hx, tag 0); buffer1 = invalid tag
    {
        float h0 = __ldg(hx + (size_t)b * H + tid);
        u64 pv;
        asm("mov.b64 %0, {%1, %2};" : "=l"(pv) : "f"(h0), "r"(0u));
        h_tag[0][tid] = pv;
        asm("mov.b64 %0, {%1, %2};" : "=l"(pv) : "f"(0.0f), "r"(0xFFFFFFFFu));
        h_tag[1][tid] = pv;
    }
    __syncthreads();
    asm volatile("barrier.cluster.arrive.aligned;" ::: "memory");
    asm volatile("barrier.cluster.wait.aligned;"   ::: "memory");

    // --- addresses (buf offset = buf * H * 8 bytes)
    const int pl = lane & 15;
    const uint32_t pollL = smem_u32(&h_tag[0][kL + pl]);
    const uint32_t pollP = smem_u32(&h_tag[0][kP + pl]);
    const uint32_t vecL  = smem_u32(&h_tag[0][kL]);
    const uint32_t vecP  = smem_u32(&h_tag[0][kP]);
    uint32_t locA = 0, peerA = 0;
    if (tid < HHALF) {
        locA  = smem_u32(&h_tag[0][j0 + tid]);
        peerA = mapa_u32(locA, rank ^ 1u);
    }

    // xp prefetch (one step ahead)
    const float* xpb = xproj + (size_t)b * H + j0 + tid;
    float xp = 0.0f;
    if (tid < HHALF) xp = __ldg(xpb);

    for (int t = 0; t < T_STEPS; t++) {
        const uint32_t buf  = (uint32_t)t & 1u;
        const uint32_t boff = buf * (H * 8);

        u64 a0 = 0ull, a1 = 0ull, a2 = 0ull, a3 = 0ull;

        // ---- LOCAL half: poll + compute (data written locally, lands fast)
        {
            const uint32_t pa = pollL + boff;
            uint32_t lo, hi;
            bool ok;
            do {
                asm volatile("ld.volatile.shared.v2.u32 {%0, %1}, [%2];"
                             : "=r"(lo), "=r"(hi) : "r"(pa) : "memory");
                ok = (hi == (uint32_t)t);
            } while (!__all_sync(0xFFFFFFFFu, ok));
        }
        {
            const uint32_t hb = vecL + boff;
            #pragma unroll
            for (int q = 0; q < 8; q++) {
                uint32_t v0, d0, v1, d1;
                asm volatile("ld.shared.v4.u32 {%0, %1, %2, %3}, [%4];"
                             : "=r"(v0), "=r"(d0), "=r"(v1), "=r"(d1)
                             : "r"(hb + 16 * q));
                u64 hv;
                asm("mov.b64 %0, {%1, %2};" : "=l"(hv) : "r"(v0), "r"(v1));
                fma2(a0, hv, wL[0][q]);
                fma2(a1, hv, wL[1][q]);
                fma2(a2, hv, wL[2][q]);
                fma2(a3, hv, wL[3][q]);
            }
        }

        // ---- PEER half: DSMEM latency now (mostly) elapsed
        {
            const uint32_t pa = pollP + boff;
            uint32_t lo, hi;
            bool ok;
            do {
                asm volatile("ld.volatile.shared.v2.u32 {%0, %1}, [%2];"
                             : "=r"(lo), "=r"(hi) : "r"(pa) : "memory");
                ok = (hi == (uint32_t)t);
            } while (!__all_sync(0xFFFFFFFFu, ok));
        }
        {
            const uint32_t hb = vecP + boff;
            #pragma unroll
            for (int q = 0; q < 8; q++) {
                uint32_t v0, d0, v1, d1;
                asm volatile("ld.shared.v4.u32 {%0, %1, %2, %3}, [%4];"
                             : "=r"(v0), "=r"(d0), "=r"(v1), "=r"(d1)
                             : "r"(hb + 16 * q));
                u64 hv;
                asm("mov.b64 %0, {%1, %2};" : "=l"(hv) : "r"(v0), "r"(v1));
                fma2(a0, hv, wP[0][q]);
                fma2(a1, hv, wP[1][q]);
                fma2(a2, hv, wP[2][q]);
                fma2(a3, hv, wP[3][q]);
            }
        }

        *reinterpret_cast<float4*>(&part[buf][s][jl]) =
            make_float4(fold2(a0), fold2(a1), fold2(a2), fold2(a3));
        __syncthreads();

        if (tid < HHALF) {
            float v01 = part[buf][0][tid] + part[buf][1][tid];
            float v23 = part[buf][2][tid] + part[buf][3][tid];
            float v45 = part[buf][4][tid] + part[buf][5][tid];
            float v67 = part[buf][6][tid] + part[buf][7][tid];
            const float hn = fast_tanh(((v01 + v23) + (v45 + v67)) + xp);

            if (t + 1 < T_STEPS) {
                u64 pv;
                asm("mov.b64 %0, {%1, %2};" : "=l"(pv) : "f"(hn), "r"((uint32_t)(t + 1)));
                const uint32_t noff = ((uint32_t)(t + 1) & 1u) * (H * 8);
                // remote first: starts the DSMEM transfer ASAP
                asm volatile("st.shared::cluster.b64 [%0], %1;"
                             :: "r"(peerA + noff), "l"(pv) : "memory");
                asm volatile("st.shared.b64 [%0], %1;"
                             :: "r"(locA + noff), "l"(pv) : "memory");
            }

            out[(size_t)t * (BATCH * H) + (size_t)b * H + j0 + tid] = hn;
            if (hlast && t == T_STEPS - 1)
                hlast[(size_t)b * H + j0 + tid] = hn;

            if (t + 1 < T_STEPS)
                xp = __ldg(xpb + (size_t)(t + 1) * (BATCH * H));
        }
        // no trailing __syncthreads: part[] parity double-buffered; h-tag gate
        // transitively orders next-step part writes after this step's reads.
    }

    // Drain before retiring (R2 lesson).
    asm volatile("barrier.cluster.arrive.aligned;" ::: "memory");
    asm volatile("barrier.cluster.wait.aligned;"   ::: "memory");
}

// ---------------------------------------------------------------------------
extern "C" void kernel_launch(void* const* d_in, const int* in_sizes, int n_in,
                              void* d_out, int out_size)
{
    const float* x    = (const float*)d_in[0];   // [T,B,256]
    const float* hx   = (const float*)d_in[1];   // [B,256]
    const float* W_ih = (const float*)d_in[2];   // [256,256]
    const float* W_hh = (const float*)d_in[3];   // [256,256]
    const float* b_ih = (const float*)d_in[4];   // [256]
    const float* b_hh = (const float*)d_in[5];   // [256]
    float* out = (float*)d_out;

    u64*   d_Wp;
    float* d_xproj;
    cudaGetSymbolAddress((void**)&d_Wp, g_Wp);
    cudaGetSymbolAddress((void**)&d_xproj, g_xproj);

    float* hlast = (out_size >= TBH + BATCH * H) ? (out + TBH) : nullptr;

    pack_wih_kernel<<<32, dim3(32, 32)>>>(W_ih, d_Wp);
    xproj_kernel<<<(T_STEPS * BATCH) / 32, 128>>>(x, d_Wp, b_ih, b_hh, d_xproj);
    rnn_scan_kernel<<<2 * BATCH, 256>>>(d_xproj, hx, W_hh, out, hlast);
    (void)in_sizes; (void)n_in;
}

// round 7
// speedup vs baseline: 1.0694x; 1.0694x over previous
#include <cuda_runtime.h>
#include <cstdint>

#define T_STEPS 2048
#define BATCH   64
#define H       256
#define HHALF   128
#define TBH     (T_STEPS * BATCH * H)

typedef unsigned long long u64;

// Scratch (no cudaMalloc allowed): packed W_ih and precomputed xproj.
__device__ u64   g_Wp[(H / 2) * H];      // Wp[u][c] = pack(W_ih[c][2u], W_ih[c][2u+1])
__device__ float g_xproj[(size_t)TBH];   // [T*B][H]

// ---------------------------------------------------------------------------
// helpers
// ---------------------------------------------------------------------------
__device__ __forceinline__ void fma2(u64& d, u64 a, u64 b)
{
    asm("fma.rn.f32x2 %0, %1, %2, %0;" : "+l"(d) : "l"(a), "l"(b));
}
__device__ __forceinline__ u64 add2(u64 a, u64 b)
{
    u64 r;
    asm("add.rn.f32x2 %0, %1, %2;" : "=l"(r) : "l"(a), "l"(b));
    return r;
}
__device__ __forceinline__ float fold2(u64 v)
{
    float lo, hi;
    asm("mov.b64 {%0, %1}, %2;" : "=f"(lo), "=f"(hi) : "l"(v));
    return lo + hi;
}
__device__ __forceinline__ uint32_t smem_u32(const void* p)
{
    uint32_t a;
    asm("{ .reg .u64 t; cvta.to.shared.u64 t, %1; cvt.u32.u64 %0, t; }"
        : "=r"(a) : "l"(p));
    return a;
}
__device__ __forceinline__ uint32_t mapa_u32(uint32_t la, uint32_t rank)
{
    uint32_t ra;
    asm("mapa.shared::cluster.u32 %0, %1, %2;" : "=r"(ra) : "r"(la), "r"(rank));
    return ra;
}
// tanh(x) = 1 - 2/(1+e^{2x}); rel err ~1e-6, graceful at large |x|.
__device__ __forceinline__ float fast_tanh(float x)
{
    float e = __expf(2.0f * x);
    return 1.0f - __fdividef(2.0f, 1.0f + e);
}

// ---------------------------------------------------------------------------
// Kernel 1: pack W_ih into pair layout (u64 transpose).
// ---------------------------------------------------------------------------
__global__ void pack_wih_kernel(const float* __restrict__ W, u64* __restrict__ Wp)
{
    __shared__ u64 tile[32][33];
    const int u0 = (blockIdx.x & 3) * 32;
    const int c0 = (blockIdx.x >> 2) * 32;
    const u64* ullW = reinterpret_cast<const u64*>(W);
    tile[threadIdx.y][threadIdx.x] = ullW[(c0 + threadIdx.y) * (H / 2) + (u0 + threadIdx.x)];
    __syncthreads();
    Wp[(u0 + threadIdx.y) * H + (c0 + threadIdx.x)] = tile[threadIdx.x][threadIdx.y];
}

// ---------------------------------------------------------------------------
// Kernel 2: xproj (R5 configuration: 256 thr, 4 rows x 8 strided cols, f32x2)
// ---------------------------------------------------------------------------
__global__ __launch_bounds__(256, 2)
void xproj_kernel(const float* __restrict__ x, const u64* __restrict__ Wp,
                  const float* __restrict__ b_ih, const float* __restrict__ b_hh,
                  float* __restrict__ xproj)
{
    __shared__ __align__(16) u64 xs[32][H / 2];

    const int tid = threadIdx.x;
    const size_t row0 = (size_t)blockIdx.x * 32;

    const float4* xg = reinterpret_cast<const float4*>(x + row0 * H);
    float4* xsf = reinterpret_cast<float4*>(&xs[0][0]);
    #pragma unroll
    for (int i = 0; i < 8; i++) xsf[tid + i * 256] = xg[tid + i * 256];
    __syncthreads();

    const int lane = tid & 31;
    const int rg   = tid >> 5;
    const int m0   = 4 * rg;

    u64 acc[4][8];
    #pragma unroll
    for (int m = 0; m < 4; m++)
        #pragma unroll
        for (int i = 0; i < 8; i++) acc[m][i] = 0ull;

    #pragma unroll 2
    for (int u = 0; u < H / 2; u++) {
        u64 w[8];
        #pragma unroll
        for (int i = 0; i < 8; i++) w[i] = __ldg(&Wp[u * H + lane + 32 * i]);
        #pragma unroll
        for (int m = 0; m < 4; m++) {
            u64 xv = xs[m0 + m][u];
            #pragma unroll
            for (int i = 0; i < 8; i++) fma2(acc[m][i], xv, w[i]);
        }
    }

    #pragma unroll
    for (int m = 0; m < 4; m++) {
        #pragma unroll
        for (int i = 0; i < 8; i++) {
            const int c = lane + 32 * i;
            float v = fold2(acc[m][i]) + b_ih[c] + b_hh[c];
            xproj[(row0 + m0 + m) * H + c] = v;
        }
    }
}

// ---------------------------------------------------------------------------
// Kernel 3: scan, 2-CTA cluster per batch row, PARTIAL-EXCHANGE topology.
// CTA rank r owns k-half == j-half [128r, 128r+128): its mat-vec consumes
// only h values it finalized itself (local). Cross-CTA data = partial sums
// for the peer's j-half, sent straight out of the mat-vec (tagged 8B words),
// before any reduce/tanh. One thread per j-column (full 128-k dot, 4 ILP
// chains). Warps 4-7 (hi-wid priority) are the senders.
// ---------------------------------------------------------------------------
__global__ void __cluster_dims__(2, 1, 1) __launch_bounds__(256, 1)
rnn_scan_kernel(const float* __restrict__ xproj, const float* __restrict__ hx,
                const float* __restrict__ W_hh, float* __restrict__ out,
                float* __restrict__ hlast)
{
    __shared__ __align__(16) float h_s[2][HHALF];   // own-half h, by parity
    __shared__ __align__(16) u64 inbox[2][HHALF];   // (val, tag) from peer

    const int tid = threadIdx.x;
    uint32_t rank;
    asm("mov.u32 %0, %%cluster_ctarank;" : "=r"(rank));
    const int b   = blockIdx.x >> 1;
    const int j0  = (int)rank * HHALF;          // own j/k half base
    const int jp0 = (int)(rank ^ 1u) * HHALF;   // peer j half base

    const bool sender = (tid >= HHALF);         // warps 4-7: peer-j dots
    const int  lj     = tid & (HHALF - 1);
    const int  j      = sender ? (jp0 + lj) : (j0 + lj);

    // --- weights: full 128-k row chunk for my single j column (64 u64 pairs)
    u64 w[64];
    {
        const ulonglong2* Wr = reinterpret_cast<const ulonglong2*>(
            W_hh + (size_t)j * H + j0);   // k-range = own half [j0, j0+128)
        #pragma unroll
        for (int q = 0; q < 32; q++) {
            ulonglong2 v = __ldg(&Wr[q]);
            w[2 * q]     = v.x;
            w[2 * q + 1] = v.y;
        }
    }

    // --- init h (own half) + inbox tags
    if (!sender) h_s[0][lj] = __ldg(hx + (size_t)b * H + j0 + lj);
    if (sender) {
        u64 inv;
        asm("mov.b64 %0, {%1, %2};" : "=l"(inv) : "f"(0.0f), "r"(0xFFFFFFFFu));
        inbox[0][lj] = inv;
        inbox[1][lj] = inv;
    }
    __syncthreads();
    asm volatile("barrier.cluster.arrive.aligned;" ::: "memory");
    asm volatile("barrier.cluster.wait.aligned;"   ::: "memory");

    // --- addresses
    const uint32_t hA   = smem_u32(&h_s[0][0]);           // + par*512 + 16q
    const uint32_t inA  = smem_u32(&inbox[0][lj]);        // my poll slot, + par*1024
    uint32_t peerIn = 0;
    if (sender) peerIn = mapa_u32(smem_u32(&inbox[0][lj]), rank ^ 1u);

    // xp prefetch (finalizers only)
    const float* xpb = xproj + (size_t)b * H + j0 + lj;
    float xp = 0.0f;
    if (!sender) xp = __ldg(xpb);

    for (int t = 0; t < T_STEPS; t++) {
        const uint32_t par  = (uint32_t)t & 1u;
        const uint32_t hoff = par * (HHALF * 4);
        const uint32_t ioff = par * (HHALF * 8);

        // --- full 128-k dot, 4 interleaved accumulator chains, LDS broadcast
        u64 a0 = 0ull, a1 = 0ull, a2 = 0ull, a3 = 0ull;
        const uint32_t hb = hA + hoff;
        #pragma unroll
        for (int q = 0; q < 16; q++) {          // 2 x v4 per iter = 4 pairs
            uint32_t r0, r1, r2, r3, r4, r5, r6, r7;
            asm volatile("ld.shared.v4.u32 {%0, %1, %2, %3}, [%4];"
                         : "=r"(r0), "=r"(r1), "=r"(r2), "=r"(r3)
                         : "r"(hb + 32 * q));
            asm volatile("ld.shared.v4.u32 {%0, %1, %2, %3}, [%4];"
                         : "=r"(r4), "=r"(r5), "=r"(r6), "=r"(r7)
                         : "r"(hb + 32 * q + 16));
            u64 h0, h1, h2, h3;
            asm("mov.b64 %0, {%1, %2};" : "=l"(h0) : "r"(r0), "r"(r1));
            asm("mov.b64 %0, {%1, %2};" : "=l"(h1) : "r"(r2), "r"(r3));
            asm("mov.b64 %0, {%1, %2};" : "=l"(h2) : "r"(r4), "r"(r5));
            asm("mov.b64 %0, {%1, %2};" : "=l"(h3) : "r"(r6), "r"(r7));
            fma2(a0, h0, w[4 * q + 0]);
            fma2(a1, h1, w[4 * q + 1]);
            fma2(a2, h2, w[4 * q + 2]);
            fma2(a3, h3, w[4 * q + 3]);
        }
        const float pj = fold2(add2(add2(a0, a1), add2(a2, a3)));

        if (sender) {
            // fire tagged partial into the peer's inbox — no reduce/tanh first
            u64 pv;
            asm("mov.b64 %0, {%1, %2};" : "=l"(pv) : "f"(pj), "r"((uint32_t)t));
            asm volatile("st.shared::cluster.b64 [%0], %1;"
                         :: "r"(peerIn + ioff), "l"(pv) : "memory");
        } else {
            // poll my inbox word for this step's tag
            float rv;
            {
                const uint32_t pa = inA + ioff;
                uint32_t lo, hi;
                do {
                    asm volatile("ld.volatile.shared.v2.u32 {%0, %1}, [%2];"
                                 : "=r"(lo), "=r"(hi) : "r"(pa) : "memory");
                } while (hi != (uint32_t)t);
                rv = __uint_as_float(lo);
            }
            const float hn = fast_tanh(pj + rv + xp);
            h_s[par ^ 1u][lj] = hn;                           // local only!
            out[(size_t)t * (BATCH * H) + (size_t)b * H + j0 + lj] = hn;
            if (hlast && t == T_STEPS - 1)
                hlast[(size_t)b * H + j0 + lj] = hn;
            if (t + 1 < T_STEPS)
                xp = __ldg(xpb + (size_t)(t + 1) * (BATCH * H));
        }
        __syncthreads();   // h_s[par^1] complete; inbox[par] reusable at t+2
    }

    // Drain before retiring (R2 lesson: peer remote stores may be in flight).
    asm volatile("barrier.cluster.arrive.aligned;" ::: "memory");
    asm volatile("barrier.cluster.wait.aligned;"   ::: "memory");
}

// ---------------------------------------------------------------------------
extern "C" void kernel_launch(void* const* d_in, const int* in_sizes, int n_in,
                              void* d_out, int out_size)
{
    const float* x    = (const float*)d_in[0];   // [T,B,256]
    const float* hx   = (const float*)d_in[1];   // [B,256]
    const float* W_ih = (const float*)d_in[2];   // [256,256]
    const float* W_hh = (const float*)d_in[3];   // [256,256]
    const float* b_ih = (const float*)d_in[4];   // [256]
    const float* b_hh = (const float*)d_in[5];   // [256]
    float* out = (float*)d_out;

    u64*   d_Wp;
    float* d_xproj;
    cudaGetSymbolAddress((void**)&d_Wp, g_Wp);
    cudaGetSymbolAddress((void**)&d_xproj, g_xproj);

    float* hlast = (out_size >= TBH + BATCH * H) ? (out + TBH) : nullptr;

    pack_wih_kernel<<<32, dim3(32, 32)>>>(W_ih, d_Wp);
    xproj_kernel<<<(T_STEPS * BATCH) / 32, 256>>>(x, d_Wp, b_ih, b_hh, d_xproj);
    rnn_scan_kernel<<<2 * BATCH, 256>>>(d_xproj, hx, W_hh, out, hlast);
    (void)in_sizes; (void)n_in;
}